// round 14
// baseline (speedup 1.0000x reference)
#include <cuda_runtime.h>
#include <cuda_bf16.h>
#include <mma.h>
#include <cstdint>
#include <cstddef>

using namespace nvcuda;

#define Bx   64
#define Sx   512
#define Dx   256
#define Hx   512
#define Gx   2048   // 4*H
#define OUTx 128
#define HB   (Bx * Hx)   // 32768

// ---------------- scratch (static device allocations are the allowed path) ---
__device__ float g_xg[(size_t)Sx * Bx * Gx];                 // layer-0 gate preacts (no bias)
__device__ __align__(16) __nv_bfloat16 g_h1Hi[2][HB];        // h1 double-buffered hi/lo
__device__ __align__(16) __nv_bfloat16 g_h1Lo[2][HB];
__device__ __align__(16) __nv_bfloat16 g_h2Hi[2][HB];        // h2 double-buffered hi/lo
__device__ __align__(16) __nv_bfloat16 g_h2Lo[2][HB];
__device__ float g_h2C[HB];                                  // h2 fp32 [b][j] for FC
__device__ unsigned g_bar[1];
__device__ __nv_bfloat16 g_A2[(size_t)Sx * Bx * 3 * Dx];     // split-A for gemm0
__device__ __nv_bfloat16 g_W2[(size_t)Gx * 3 * Dx];          // split-W for gemm0

__global__ void init_kernel() { if (threadIdx.x == 0) g_bar[0] = 0u; }

// ---------------- cp.async helpers -------------------------------------------
#define CP16(dst, src) \
    asm volatile("cp.async.cg.shared.global [%0], [%1], 16;" :: "r"(dst), "l"(src))
#define CP_COMMIT() asm volatile("cp.async.commit_group;" ::: "memory")
#define CP_WAIT0()  asm volatile("cp.async.wait_group 0;" ::: "memory")
#define CP_WAIT1()  asm volatile("cp.async.wait_group 1;" ::: "memory")

// ---------------- fp32 -> (hi,lo) bf16 split conversions ---------------------
__global__ void conv_w_kernel(const float* __restrict__ W, __nv_bfloat16* __restrict__ W2, int K)
{
    int n = blockIdx.x;
    const float* src = W + (size_t)n * K;
    __nv_bfloat16* dst = W2 + (size_t)n * 3 * K;
    for (int k = threadIdx.x; k < K; k += blockDim.x) {
        float v = src[k];
        __nv_bfloat16 hi = __float2bfloat16(v);
        __nv_bfloat16 lo = __float2bfloat16(v - __bfloat162float(hi));
        dst[k] = hi; dst[K + k] = lo; dst[2 * K + k] = hi;
    }
}

__global__ void conv_a_kernel(const float* __restrict__ A, __nv_bfloat16* __restrict__ A2, int K)
{
    int m = blockIdx.x;   // m = s*64 + b ; A is x[b][s][k]
    const float* src = A + (size_t)(m & 63) * (Sx * Dx) + (size_t)(m >> 6) * Dx;
    __nv_bfloat16* dst = A2 + (size_t)m * 3 * K;
    for (int k = threadIdx.x; k < K; k += blockDim.x) {
        float v = src[k];
        __nv_bfloat16 hi = __float2bfloat16(v);
        __nv_bfloat16 lo = __float2bfloat16(v - __bfloat162float(hi));
        dst[k] = hi; dst[K + k] = hi; dst[2 * K + k] = lo;
    }
}

// ---------------- HMMA (wmma) GEMM for layer-0 input projection (R13) --------
#define LDP 40

__global__ void __launch_bounds__(256, 2) wmma_gemm_kernel(
    const __nv_bfloat16* __restrict__ A2, const __nv_bfloat16* __restrict__ W2,
    float* __restrict__ C, int Ktot)
{
    __shared__ __align__(16) __nv_bfloat16 As[2][128 * LDP];
    __shared__ __align__(16) __nv_bfloat16 Bs[2][128 * LDP];

    const int tid = threadIdx.x;
    const int wid = tid >> 5;
    const int m0 = blockIdx.y * 128;
    const int n0 = blockIdx.x * 128;
    const int wm = (wid >> 2) * 64;
    const int wn = (wid & 3) * 32;

    wmma::fragment<wmma::accumulator, 16, 16, 16, float> acc[4][2];
#pragma unroll
    for (int i = 0; i < 4; ++i)
#pragma unroll
        for (int j = 0; j < 2; ++j) wmma::fill_fragment(acc[i][j], 0.f);

    const int ca = tid, cb = tid + 256;
    const int ra = ca >> 2, qa = ca & 3;
    const int rb = cb >> 2, qb = cb & 3;
    const char* Ag = (const char*)A2;
    const char* Bg = (const char*)W2;
    const size_t aoff0 = ((size_t)(m0 + ra) * Ktot + qa * 8) * 2;
    const size_t aoff1 = ((size_t)(m0 + rb) * Ktot + qb * 8) * 2;
    const size_t boff0 = ((size_t)(n0 + ra) * Ktot + qa * 8) * 2;
    const size_t boff1 = ((size_t)(n0 + rb) * Ktot + qb * 8) * 2;
    const int s0 = ra * (LDP * 2) + qa * 16;
    const int s1 = rb * (LDP * 2) + qb * 16;

    uint32_t sA[2], sB[2];
    sA[0] = (uint32_t)__cvta_generic_to_shared(As[0]);
    sA[1] = (uint32_t)__cvta_generic_to_shared(As[1]);
    sB[0] = (uint32_t)__cvta_generic_to_shared(Bs[0]);
    sB[1] = (uint32_t)__cvta_generic_to_shared(Bs[1]);

    const int T = Ktot >> 5;
    {
        CP16(sA[0] + s0, Ag + aoff0);
        CP16(sA[0] + s1, Ag + aoff1);
        CP16(sB[0] + s0, Bg + boff0);
        CP16(sB[0] + s1, Bg + boff1);
        CP_COMMIT();
    }

    for (int t = 0; t < T; ++t) {
        const int buf = t & 1;
        const bool more = (t + 1 < T);
        if (more) {
            size_t ko = (size_t)(t + 1) * 64;
            const int nb = buf ^ 1;
            CP16(sA[nb] + s0, Ag + aoff0 + ko);
            CP16(sA[nb] + s1, Ag + aoff1 + ko);
            CP16(sB[nb] + s0, Bg + boff0 + ko);
            CP16(sB[nb] + s1, Bg + boff1 + ko);
            CP_COMMIT();
            CP_WAIT1();
        } else {
            CP_WAIT0();
        }
        __syncthreads();
#pragma unroll
        for (int ks = 0; ks < 2; ++ks) {
            wmma::fragment<wmma::matrix_a, 16, 16, 16, __nv_bfloat16, wmma::row_major> af[4];
            wmma::fragment<wmma::matrix_b, 16, 16, 16, __nv_bfloat16, wmma::col_major> bf[2];
#pragma unroll
            for (int i = 0; i < 4; ++i)
                wmma::load_matrix_sync(af[i], &As[buf][(wm + i * 16) * LDP + ks * 16], LDP);
#pragma unroll
            for (int j = 0; j < 2; ++j)
                wmma::load_matrix_sync(bf[j], &Bs[buf][(wn + j * 16) * LDP + ks * 16], LDP);
#pragma unroll
            for (int i = 0; i < 4; ++i)
#pragma unroll
                for (int j = 0; j < 2; ++j)
                    wmma::mma_sync(acc[i][j], af[i], bf[j], acc[i][j]);
        }
        __syncthreads();
    }

#pragma unroll
    for (int i = 0; i < 4; ++i)
#pragma unroll
        for (int j = 0; j < 2; ++j)
            wmma::store_matrix_sync(
                C + (size_t)(m0 + wm + i * 16) * Gx + n0 + wn + j * 16,
                acc[i][j], Gx, wmma::mem_row_major);
}

// ---------------- batch-tiled fused 2-layer pipelined LSTM scan ---------------
// 128 CTAs = 64 unit-groups (8 units, 32 gate rows per layer) x 2 batch halves
// (32 batches). Same tensor work per CTA as R13, but staged tiles are 32 rows:
// L2 broadcast and crossbar traffic HALVED. 3-pass split-bf16, fp32 acc.
#define PWE     520
#define SM_AHI  0                      // 32*520*2 = 33280 (aliased by P: 64KB)
#define SM_ALO  33280                  // 33280
#define SM_WLO  66560                  // 3*32*520*2 = 99840
#define SM_WHI2 166400                 // 33280 (Whh1-hi tile, smem-resident)
#define SM_GSM  199680                 // 64*36*4 = 9216
#define SM_CSM  208896                 // 2*32*8*4 = 2048
#define SM_BSM  210944                 // 64*4 = 256
#define FUSED_SMEM 211200

typedef wmma::fragment<wmma::matrix_a, 16, 16, 16, __nv_bfloat16, wmma::row_major> frag_a;
typedef wmma::fragment<wmma::matrix_b, 16, 16, 16, __nv_bfloat16, wmma::col_major> frag_b;
typedef wmma::fragment<wmma::accumulator, 16, 16, 16, float> frag_c;

__device__ __forceinline__ float tanhap(float x) {
    float y; asm("tanh.approx.f32 %0, %1;" : "=f"(y) : "f"(x)); return y;
}
__device__ __forceinline__ float sigf(float x) {
    return fmaf(tanhap(x * 0.5f), 0.5f, 0.5f);
}

// async stage of 32x512 bf16 tile into padded smem (1040B rows)
__device__ __forceinline__ void stage32(uint32_t dstb, const __nv_bfloat16* src, int tid) {
#pragma unroll
    for (int i = 0; i < 8; ++i) {
        int c = tid + i * 256;                     // 2048 16B chunks
        int row = c >> 6, col = c & 63;
        CP16(dstb + row * 1040 + col * 16, src + row * Hx + col * 8);
    }
    CP_COMMIT();
}

__global__ void __launch_bounds__(256, 1) fused_scan(
    const float* __restrict__ xg,
    const float* __restrict__ Whh0, const float* __restrict__ Wih1,
    const float* __restrict__ Whh1,
    const float* __restrict__ bih0, const float* __restrict__ bhh0,
    const float* __restrict__ bih1, const float* __restrict__ bhh1)
{
    extern __shared__ char sm[];
    __nv_bfloat16* AsmHi = (__nv_bfloat16*)(sm + SM_AHI);
    __nv_bfloat16* AsmLo = (__nv_bfloat16*)(sm + SM_ALO);
    __nv_bfloat16* WloS  = (__nv_bfloat16*)(sm + SM_WLO);
    __nv_bfloat16* Whi2S = (__nv_bfloat16*)(sm + SM_WHI2);
    float* gsm = (float*)(sm + SM_GSM);            // [64 r][36]
    float* csm = (float*)(sm + SM_CSM);            // [2][32 b][8 u]
    float* bsm = (float*)(sm + SM_BSM);            // [64 r]
    float* P   = (float*)(sm + SM_AHI);            // [8 w][32 b][64 r] aliases A
    const uint32_t sHi = (uint32_t)__cvta_generic_to_shared(AsmHi);
    const uint32_t sLo = (uint32_t)__cvta_generic_to_shared(AsmLo);

    const int tid = threadIdx.x;
    const int wid = tid >> 5;
    const int kb  = wid * 64;
    const int ug  = blockIdx.x >> 1;               // unit group 0..63
    const int bh  = blockIdx.x & 1;                // batch half
    const int u0  = ug * 8;
    const int b0  = bh * 32;
    unsigned* bar = g_bar;

    // ---- prologue: split 3 W matrices ----------------------------------------
    frag_b whiR[2][4][2];                          // Whh0, Wih1 hi: reg-resident
    const float* Wsrcs[3] = {Whh0, Wih1, Whh1};
#pragma unroll
    for (int m = 0; m < 3; ++m) {
        const float* Wsrc = Wsrcs[m];
        __nv_bfloat16* hiDst = (m == 2) ? Whi2S : AsmHi;
        __nv_bfloat16* loDst = WloS + m * 32 * PWE;
#pragma unroll 4
        for (int i = 0; i < 64; ++i) {
            int idx = tid + i * 256;               // 32 rows x 512 k
            int r = idx >> 9, k = idx & 511;
            float v = Wsrc[(size_t)((r >> 3) * Hx + u0 + (r & 7)) * Hx + k];
            __nv_bfloat16 hi = __float2bfloat16(v);
            hiDst[r * PWE + k] = hi;
            loDst[r * PWE + k] = __float2bfloat16(v - __bfloat162float(hi));
        }
        __syncthreads();
        if (m < 2) {
#pragma unroll
            for (int j = 0; j < 4; ++j)
#pragma unroll
                for (int nt = 0; nt < 2; ++nt)
                    wmma::load_matrix_sync(whiR[m][j][nt],
                        AsmHi + nt * 16 * PWE + kb + j * 16, PWE);
            __syncthreads();
        }
    }
    if (tid < 64) {
        int r = tid & 31, g = r >> 3, u = r & 7;
        bsm[tid] = (tid < 32)
            ? (bih0[g * Hx + u0 + u] + bhh0[g * Hx + u0 + u])
            : (bih1[g * Hx + u0 + u] + bhh1[g * Hx + u0 + u]);
    }
    csm[tid] = 0.f; csm[tid + 256] = 0.f;
    __syncthreads();

    // ---- main pipeline loop: 513 ticks ---------------------------------------
    for (int t = 0; t <= Sx; ++t) {
        const bool l0   = (t < Sx);
        const bool hasA = (t >= 1);
        const bool hasB = (t >= 2);

        // prefetch xg for L0 gate threads (tid<128: b=tid>>2, units 2q,2q+1)
        float2 xf0, xf1, xf2, xf3;
        if (l0 && tid < 128) {
            int b = tid >> 2, q = tid & 3;
            const float* xp = xg + ((size_t)(t * Bx + b0 + b)) * Gx + u0 + 2 * q;
            xf0 = __ldcg((const float2*)(xp));
            xf1 = __ldcg((const float2*)(xp + Hx));
            xf2 = __ldcg((const float2*)(xp + 2 * Hx));
            xf3 = __ldcg((const float2*)(xp + 3 * Hx));
        }

        frag_c aL0[2][2], aL1[2][2];
#pragma unroll
        for (int mt = 0; mt < 2; ++mt)
#pragma unroll
            for (int nt = 0; nt < 2; ++nt) {
                wmma::fill_fragment(aL0[mt][nt], 0.f);
                wmma::fill_fragment(aL1[mt][nt], 0.f);
            }

        if (hasA) {
            stage32(sHi, g_h1Hi[(t - 1) & 1] + b0 * Hx, tid);   // g1
            stage32(sLo, g_h1Lo[(t - 1) & 1] + b0 * Hx, tid);   // g2
            CP_WAIT1(); __syncthreads();                        // hi(A) ready

            // ---- HI-A: ah x {W0hi,W0lo (if l0), W1hi, W1lo} -------------------
#pragma unroll
            for (int j = 0; j < 4; ++j) {
                frag_a ah[2];
#pragma unroll
                for (int mt = 0; mt < 2; ++mt)
                    wmma::load_matrix_sync(ah[mt], AsmHi + mt * 16 * PWE + kb + j * 16, PWE);
                if (l0) {
#pragma unroll
                    for (int nt = 0; nt < 2; ++nt) {
#pragma unroll
                        for (int mt = 0; mt < 2; ++mt)
                            wmma::mma_sync(aL0[mt][nt], ah[mt], whiR[0][j][nt], aL0[mt][nt]);
                        frag_b wl;
                        wmma::load_matrix_sync(wl, WloS + 0 * 32 * PWE + nt * 16 * PWE + kb + j * 16, PWE);
#pragma unroll
                        for (int mt = 0; mt < 2; ++mt)
                            wmma::mma_sync(aL0[mt][nt], ah[mt], wl, aL0[mt][nt]);
                    }
                }
#pragma unroll
                for (int nt = 0; nt < 2; ++nt) {
#pragma unroll
                    for (int mt = 0; mt < 2; ++mt)
                        wmma::mma_sync(aL1[mt][nt], ah[mt], whiR[1][j][nt], aL1[mt][nt]);
                    frag_b wl;
                    wmma::load_matrix_sync(wl, WloS + 1 * 32 * PWE + nt * 16 * PWE + kb + j * 16, PWE);
#pragma unroll
                    for (int mt = 0; mt < 2; ++mt)
                        wmma::mma_sync(aL1[mt][nt], ah[mt], wl, aL1[mt][nt]);
                }
            }
            __syncthreads();                                    // done reading AHi

            if (hasB) { stage32(sHi, g_h2Hi[t & 1] + b0 * Hx, tid); CP_WAIT1(); }
            else      { CP_WAIT0(); }
            __syncthreads();                                    // lo(A) ready

            // ---- LO-A: al x {W0hi (if l0), W1hi} ------------------------------
#pragma unroll
            for (int j = 0; j < 4; ++j) {
                frag_a al[2];
#pragma unroll
                for (int mt = 0; mt < 2; ++mt)
                    wmma::load_matrix_sync(al[mt], AsmLo + mt * 16 * PWE + kb + j * 16, PWE);
#pragma unroll
                for (int nt = 0; nt < 2; ++nt) {
                    if (l0)
#pragma unroll
                        for (int mt = 0; mt < 2; ++mt)
                            wmma::mma_sync(aL0[mt][nt], al[mt], whiR[0][j][nt], aL0[mt][nt]);
#pragma unroll
                    for (int mt = 0; mt < 2; ++mt)
                        wmma::mma_sync(aL1[mt][nt], al[mt], whiR[1][j][nt], aL1[mt][nt]);
                }
            }
            __syncthreads();                                    // done reading ALo

            if (hasB) {
                stage32(sLo, g_h2Lo[t & 1] + b0 * Hx, tid);
                CP_WAIT1(); __syncthreads();                    // hi(B) ready

                // ---- HI-B: ah x {W2hi, W2lo} ----------------------------------
#pragma unroll
                for (int j = 0; j < 4; ++j) {
                    frag_a ah[2];
#pragma unroll
                    for (int mt = 0; mt < 2; ++mt)
                        wmma::load_matrix_sync(ah[mt], AsmHi + mt * 16 * PWE + kb + j * 16, PWE);
#pragma unroll
                    for (int nt = 0; nt < 2; ++nt) {
                        frag_b w2;
                        wmma::load_matrix_sync(w2, Whi2S + nt * 16 * PWE + kb + j * 16, PWE);
#pragma unroll
                        for (int mt = 0; mt < 2; ++mt)
                            wmma::mma_sync(aL1[mt][nt], ah[mt], w2, aL1[mt][nt]);
                        frag_b wl;
                        wmma::load_matrix_sync(wl, WloS + 2 * 32 * PWE + nt * 16 * PWE + kb + j * 16, PWE);
#pragma unroll
                        for (int mt = 0; mt < 2; ++mt)
                            wmma::mma_sync(aL1[mt][nt], ah[mt], wl, aL1[mt][nt]);
                    }
                }
                CP_WAIT0(); __syncthreads();                    // lo(B) ready

                // ---- LO-B: al x W2hi -------------------------------------------
#pragma unroll
                for (int j = 0; j < 4; ++j) {
                    frag_a al[2];
#pragma unroll
                    for (int mt = 0; mt < 2; ++mt)
                        wmma::load_matrix_sync(al[mt], AsmLo + mt * 16 * PWE + kb + j * 16, PWE);
#pragma unroll
                    for (int nt = 0; nt < 2; ++nt) {
                        frag_b w2;
                        wmma::load_matrix_sync(w2, Whi2S + nt * 16 * PWE + kb + j * 16, PWE);
#pragma unroll
                        for (int mt = 0; mt < 2; ++mt)
                            wmma::mma_sync(aL1[mt][nt], al[mt], w2, aL1[mt][nt]);
                    }
                }
                __syncthreads();                                // done reading ALo
            }

            // ---- partial store + 8-way reduce ---------------------------------
#pragma unroll
            for (int mt = 0; mt < 2; ++mt)
#pragma unroll
                for (int nt = 0; nt < 2; ++nt) {
                    wmma::store_matrix_sync(P + wid * 2048 + mt * 16 * 64 + nt * 16,
                                            aL0[mt][nt], 64, wmma::mem_row_major);
                    wmma::store_matrix_sync(P + wid * 2048 + mt * 16 * 64 + 32 + nt * 16,
                                            aL1[mt][nt], 64, wmma::mem_row_major);
                }
            __syncthreads();
#pragma unroll
            for (int i = 0; i < 8; ++i) {
                int cell = tid + i * 256;              // b = cell>>6, r = cell&63
                float v = 0.f;
#pragma unroll
                for (int w = 0; w < 8; ++w) v += P[w * 2048 + cell];
                gsm[(cell & 63) * 36 + (cell >> 6)] = v;
            }
            __syncthreads();
        }

        // ---- gates: tid<128 -> L0 (b=tid>>2, units 2q,2q+1); tid>=128 -> L1 --
        if (tid < 128 && l0) {
            const int b = tid >> 2, q = tid & 3;
            const float* xfp[4] = {&xf0.x, &xf1.x, &xf2.x, &xf3.x};
            __nv_bfloat16 hp[2], lp[2];
#pragma unroll
            for (int uu = 0; uu < 2; ++uu) {
                int u = 2 * q + uu;
                float p0 = (hasA ? gsm[(0  + u) * 36 + b] : 0.f) + bsm[0  + u] + xfp[0][uu];
                float p1 = (hasA ? gsm[(8  + u) * 36 + b] : 0.f) + bsm[8  + u] + xfp[1][uu];
                float p2 = (hasA ? gsm[(16 + u) * 36 + b] : 0.f) + bsm[16 + u] + xfp[2][uu];
                float p3 = (hasA ? gsm[(24 + u) * 36 + b] : 0.f) + bsm[24 + u] + xfp[3][uu];
                float ig = sigf(p0), fg = sigf(p1), gg = tanhap(p2), og = sigf(p3);
                float c = csm[b * 8 + u];
                c = fg * c + ig * gg;
                csm[b * 8 + u] = c;
                float h = og * tanhap(c);
                hp[uu] = __float2bfloat16(h);
                lp[uu] = __float2bfloat16(h - __bfloat162float(hp[uu]));
            }
            *(uint32_t*)(g_h1Hi[t & 1] + (size_t)(b0 + b) * Hx + u0 + 2 * q) = *(uint32_t*)hp;
            *(uint32_t*)(g_h1Lo[t & 1] + (size_t)(b0 + b) * Hx + u0 + 2 * q) = *(uint32_t*)lp;
        } else if (tid >= 128 && hasA) {
            const int lt = tid - 128;
            const int b = lt >> 2, q = lt & 3;
            __nv_bfloat16 hp[2], lp[2];
            float hv[2];
#pragma unroll
            for (int uu = 0; uu < 2; ++uu) {
                int u = 2 * q + uu;
                float p0 = gsm[(32 + 0  + u) * 36 + b] + bsm[32 + 0  + u];
                float p1 = gsm[(32 + 8  + u) * 36 + b] + bsm[32 + 8  + u];
                float p2 = gsm[(32 + 16 + u) * 36 + b] + bsm[32 + 16 + u];
                float p3 = gsm[(32 + 24 + u) * 36 + b] + bsm[32 + 24 + u];
                float ig = sigf(p0), fg = sigf(p1), gg = tanhap(p2), og = sigf(p3);
                float c = csm[256 + b * 8 + u];
                c = fg * c + ig * gg;
                csm[256 + b * 8 + u] = c;
                hv[uu] = og * tanhap(c);
                hp[uu] = __float2bfloat16(hv[uu]);
                lp[uu] = __float2bfloat16(hv[uu] - __bfloat162float(hp[uu]));
            }
            *(uint32_t*)(g_h2Hi[(t - 1) & 1] + (size_t)(b0 + b) * Hx + u0 + 2 * q) = *(uint32_t*)hp;
            *(uint32_t*)(g_h2Lo[(t - 1) & 1] + (size_t)(b0 + b) * Hx + u0 + 2 * q) = *(uint32_t*)lp;
            *(float2*)(g_h2C + (size_t)(b0 + b) * Hx + u0 + 2 * q) = make_float2(hv[0], hv[1]);
        }

        // ---- grid barrier ----------------------------------------------------
        __syncthreads();
        if (tid == 0) {
            __threadfence();
            atomicAdd(bar, 1u);
            unsigned target = 128u * (unsigned)(t + 1);
            while (*((volatile unsigned*)bar) < target) {}
            __threadfence();
        }
        __syncthreads();
    }
}

// ---------------- final FC ---------------------------------------------------
__global__ void fc_kernel(const float* __restrict__ hC, const float* __restrict__ fw,
                          const float* __restrict__ fb, float* __restrict__ out)
{
    __shared__ float hb[Hx];
    int b = blockIdx.x;
    int o = threadIdx.x;
    for (int j = threadIdx.x; j < Hx; j += OUTx) hb[j] = hC[(size_t)b * Hx + j];
    __syncthreads();
    float acc = fb[o];
    const float* wr = fw + (size_t)o * Hx;
#pragma unroll 4
    for (int j = 0; j < Hx; j += 4) {
        float4 w = *(const float4*)(wr + j);
        float4 h = *(const float4*)(hb + j);
        acc += w.x * h.x + w.y * h.y + w.z * h.z + w.w * h.w;
    }
    out[b * OUTx + o] = acc;
}

// ---------------- launch ------------------------------------------------------
extern "C" void kernel_launch(void* const* d_in, const int* in_sizes, int n_in,
                              void* d_out, int out_size)
{
    const float* x    = (const float*)d_in[0];
    const float* Wih0 = (const float*)d_in[1];
    const float* Whh0 = (const float*)d_in[2];
    const float* bih0 = (const float*)d_in[3];
    const float* bhh0 = (const float*)d_in[4];
    const float* Wih1 = (const float*)d_in[5];
    const float* Whh1 = (const float*)d_in[6];
    const float* bih1 = (const float*)d_in[7];
    const float* bhh1 = (const float*)d_in[8];
    const float* fcw  = (const float*)d_in[9];
    const float* fcb  = (const float*)d_in[10];
    float* out = (float*)d_out;

    cudaFuncSetAttribute((const void*)fused_scan,
                         cudaFuncAttributeMaxDynamicSharedMemorySize, FUSED_SMEM);

    void *xg_p, *a2_p, *w2_p, *h2c_p;
    cudaGetSymbolAddress(&xg_p, g_xg);
    cudaGetSymbolAddress(&a2_p, g_A2);
    cudaGetSymbolAddress(&w2_p, g_W2);
    cudaGetSymbolAddress(&h2c_p, g_h2C);

    init_kernel<<<1, 32>>>();

    // layer-0 input projection on tensor cores (split-bf16, 3-pass)
    conv_w_kernel<<<Gx, 128>>>(Wih0, (__nv_bfloat16*)w2_p, Dx);
    conv_a_kernel<<<Sx * Bx, 128>>>(x, (__nv_bfloat16*)a2_p, Dx);
    dim3 mgrid(Gx / 128, (Sx * Bx) / 128);   // (16, 256)
    wmma_gemm_kernel<<<mgrid, 256>>>(
        (const __nv_bfloat16*)a2_p, (const __nv_bfloat16*)w2_p,
        (float*)xg_p, 3 * Dx);

    // batch-tiled fused 2-layer pipelined scan (513 ticks, 128 persistent CTAs)
    fused_scan<<<128, 256, FUSED_SMEM>>>(
        (const float*)xg_p, Whh0, Wih1, Whh1, bih0, bhh0, bih1, bhh1);

    fc_kernel<<<Bx, OUTx>>>((const float*)h2c_p, fcw, fcb, out);
}

// round 15
// speedup vs baseline: 1.3337x; 1.3337x over previous
#include <cuda_runtime.h>
#include <cuda_bf16.h>
#include <mma.h>
#include <cstdint>
#include <cstddef>

using namespace nvcuda;

#define Bx   64
#define Sx   512
#define Dx   256
#define Hx   512
#define Gx   2048   // 4*H
#define OUTx 128
#define HB   (Bx * Hx)   // 32768

// ---------------- scratch (static device allocations are the allowed path) ---
__device__ float g_xg[(size_t)Sx * Bx * Gx];                 // layer-0 gate preacts (no bias)
__device__ __align__(16) __nv_bfloat16 g_h1Hi[2][HB];        // h1 double-buffered hi/lo
__device__ __align__(16) __nv_bfloat16 g_h1Lo[2][HB];
__device__ __align__(16) __nv_bfloat16 g_h2Hi[2][HB];        // h2 double-buffered hi/lo
__device__ __align__(16) __nv_bfloat16 g_h2Lo[2][HB];
__device__ float g_h2C[HB];                                  // h2 fp32 [b][j] for FC
__device__ unsigned g_bar[1];
__device__ __nv_bfloat16 g_A2[(size_t)Sx * Bx * 3 * Dx];     // split-A for gemm0
__device__ __nv_bfloat16 g_W2[(size_t)Gx * 3 * Dx];          // split-W for gemm0

__global__ void init_kernel() { if (threadIdx.x == 0) g_bar[0] = 0u; }

// ---------------- cp.async helpers -------------------------------------------
#define CP16(dst, src) \
    asm volatile("cp.async.cg.shared.global [%0], [%1], 16;" :: "r"(dst), "l"(src))
#define CP_COMMIT() asm volatile("cp.async.commit_group;" ::: "memory")
#define CP_WAIT0()  asm volatile("cp.async.wait_group 0;" ::: "memory")
#define CP_WAIT1()  asm volatile("cp.async.wait_group 1;" ::: "memory")

// ---------------- fp32 -> (hi,lo) bf16 split conversions ---------------------
__global__ void conv_w_kernel(const float* __restrict__ W, __nv_bfloat16* __restrict__ W2, int K)
{
    int n = blockIdx.x;
    const float* src = W + (size_t)n * K;
    __nv_bfloat16* dst = W2 + (size_t)n * 3 * K;
    for (int k = threadIdx.x; k < K; k += blockDim.x) {
        float v = src[k];
        __nv_bfloat16 hi = __float2bfloat16(v);
        __nv_bfloat16 lo = __float2bfloat16(v - __bfloat162float(hi));
        dst[k] = hi; dst[K + k] = lo; dst[2 * K + k] = hi;
    }
}

__global__ void conv_a_kernel(const float* __restrict__ A, __nv_bfloat16* __restrict__ A2, int K)
{
    int m = blockIdx.x;   // m = s*64 + b ; A is x[b][s][k]
    const float* src = A + (size_t)(m & 63) * (Sx * Dx) + (size_t)(m >> 6) * Dx;
    __nv_bfloat16* dst = A2 + (size_t)m * 3 * K;
    for (int k = threadIdx.x; k < K; k += blockDim.x) {
        float v = src[k];
        __nv_bfloat16 hi = __float2bfloat16(v);
        __nv_bfloat16 lo = __float2bfloat16(v - __bfloat162float(hi));
        dst[k] = hi; dst[K + k] = hi; dst[2 * K + k] = lo;
    }
}

// ---------------- HMMA (wmma) GEMM for layer-0 input projection ---------------
// cp.async double-buffered; <=128 regs so 2 CTAs/SM.
#define LDP 40

__global__ void __launch_bounds__(256, 2) wmma_gemm_kernel(
    const __nv_bfloat16* __restrict__ A2, const __nv_bfloat16* __restrict__ W2,
    float* __restrict__ C, int Ktot)
{
    __shared__ __align__(16) __nv_bfloat16 As[2][128 * LDP];
    __shared__ __align__(16) __nv_bfloat16 Bs[2][128 * LDP];

    const int tid = threadIdx.x;
    const int wid = tid >> 5;
    const int m0 = blockIdx.y * 128;
    const int n0 = blockIdx.x * 128;
    const int wm = (wid >> 2) * 64;
    const int wn = (wid & 3) * 32;

    wmma::fragment<wmma::accumulator, 16, 16, 16, float> acc[4][2];
#pragma unroll
    for (int i = 0; i < 4; ++i)
#pragma unroll
        for (int j = 0; j < 2; ++j) wmma::fill_fragment(acc[i][j], 0.f);

    const int ca = tid, cb = tid + 256;
    const int ra = ca >> 2, qa = ca & 3;
    const int rb = cb >> 2, qb = cb & 3;
    const char* Ag = (const char*)A2;
    const char* Bg = (const char*)W2;
    const size_t aoff0 = ((size_t)(m0 + ra) * Ktot + qa * 8) * 2;
    const size_t aoff1 = ((size_t)(m0 + rb) * Ktot + qb * 8) * 2;
    const size_t boff0 = ((size_t)(n0 + ra) * Ktot + qa * 8) * 2;
    const size_t boff1 = ((size_t)(n0 + rb) * Ktot + qb * 8) * 2;
    const int s0 = ra * (LDP * 2) + qa * 16;
    const int s1 = rb * (LDP * 2) + qb * 16;

    uint32_t sA[2], sB[2];
    sA[0] = (uint32_t)__cvta_generic_to_shared(As[0]);
    sA[1] = (uint32_t)__cvta_generic_to_shared(As[1]);
    sB[0] = (uint32_t)__cvta_generic_to_shared(Bs[0]);
    sB[1] = (uint32_t)__cvta_generic_to_shared(Bs[1]);

    const int T = Ktot >> 5;
    {
        CP16(sA[0] + s0, Ag + aoff0);
        CP16(sA[0] + s1, Ag + aoff1);
        CP16(sB[0] + s0, Bg + boff0);
        CP16(sB[0] + s1, Bg + boff1);
        CP_COMMIT();
    }

    for (int t = 0; t < T; ++t) {
        const int buf = t & 1;
        const bool more = (t + 1 < T);
        if (more) {
            size_t ko = (size_t)(t + 1) * 64;
            const int nb = buf ^ 1;
            CP16(sA[nb] + s0, Ag + aoff0 + ko);
            CP16(sA[nb] + s1, Ag + aoff1 + ko);
            CP16(sB[nb] + s0, Bg + boff0 + ko);
            CP16(sB[nb] + s1, Bg + boff1 + ko);
            CP_COMMIT();
            CP_WAIT1();
        } else {
            CP_WAIT0();
        }
        __syncthreads();
#pragma unroll
        for (int ks = 0; ks < 2; ++ks) {
            wmma::fragment<wmma::matrix_a, 16, 16, 16, __nv_bfloat16, wmma::row_major> af[4];
            wmma::fragment<wmma::matrix_b, 16, 16, 16, __nv_bfloat16, wmma::col_major> bf[2];
#pragma unroll
            for (int i = 0; i < 4; ++i)
                wmma::load_matrix_sync(af[i], &As[buf][(wm + i * 16) * LDP + ks * 16], LDP);
#pragma unroll
            for (int j = 0; j < 2; ++j)
                wmma::load_matrix_sync(bf[j], &Bs[buf][(wn + j * 16) * LDP + ks * 16], LDP);
#pragma unroll
            for (int i = 0; i < 4; ++i)
#pragma unroll
                for (int j = 0; j < 2; ++j)
                    wmma::mma_sync(acc[i][j], af[i], bf[j], acc[i][j]);
        }
        __syncthreads();
    }

#pragma unroll
    for (int i = 0; i < 4; ++i)
#pragma unroll
        for (int j = 0; j < 2; ++j)
            wmma::store_matrix_sync(
                C + (size_t)(m0 + wm + i * 16) * Gx + n0 + wn + j * 16,
                acc[i][j], Gx, wmma::mem_row_major);
}

// ---------------- balanced fused 2-layer pipelined LSTM scan (R13) ------------
// 128 identical CTAs; each owns 4 hidden units of BOTH layers. Tick t: L0 step t,
// L1 step t-1. cp.async 4-phase pipeline overlaps tile staging with mma.
#define PWE    520
#define SM_AHI 0
#define SM_ALO 66560
#define SM_WLO 133120                  // [3][16][520] bf16 W-lo tiles (resident)
#define SM_GSM 183040                  // [32][65] floats
#define SM_CSM 191360                  // [2][64][4] floats
#define SM_BSM 193408                  // [32] floats
#define FUSED_SMEM 193664

typedef wmma::fragment<wmma::matrix_a, 16, 16, 16, __nv_bfloat16, wmma::row_major> frag_a;
typedef wmma::fragment<wmma::matrix_b, 16, 16, 16, __nv_bfloat16, wmma::col_major> frag_b;
typedef wmma::fragment<wmma::accumulator, 16, 16, 16, float> frag_c;

__device__ __forceinline__ float tanhap(float x) {
    float y; asm("tanh.approx.f32 %0, %1;" : "=f"(y) : "f"(x)); return y;
}
__device__ __forceinline__ float sigf(float x) {
    return fmaf(tanhap(x * 0.5f), 0.5f, 0.5f);
}

// issue async stage of 64x512 bf16 [b][j] tile into padded smem (1040B rows)
__device__ __forceinline__ void stage_issue(uint32_t dstb, const __nv_bfloat16* src, int tid) {
#pragma unroll
    for (int i = 0; i < 16; ++i) {
        int c = tid + i * 256;
        int row = c >> 6, col = c & 63;
        CP16(dstb + row * 1040 + col * 16, src + row * Hx + col * 8);
    }
    CP_COMMIT();
}

__global__ void __launch_bounds__(256, 1) fused_scan(
    const float* __restrict__ xg,
    const float* __restrict__ Whh0, const float* __restrict__ Wih1,
    const float* __restrict__ Whh1,
    const float* __restrict__ bih0, const float* __restrict__ bhh0,
    const float* __restrict__ bih1, const float* __restrict__ bhh1)
{
    extern __shared__ char sm[];
    __nv_bfloat16* AsmHi = (__nv_bfloat16*)(sm + SM_AHI);
    __nv_bfloat16* AsmLo = (__nv_bfloat16*)(sm + SM_ALO);
    __nv_bfloat16* WloS  = (__nv_bfloat16*)(sm + SM_WLO);
    float* gsm = (float*)(sm + SM_GSM);
    float* csm = (float*)(sm + SM_CSM);
    float* bsm = (float*)(sm + SM_BSM);
    float* P   = (float*)(sm + SM_AHI);            // partials alias A region
    const uint32_t sHi = (uint32_t)__cvta_generic_to_shared(AsmHi);
    const uint32_t sLo = (uint32_t)__cvta_generic_to_shared(AsmLo);

    const int tid = threadIdx.x;
    const int wid = tid >> 5;
    const int kb  = wid * 64;
    const int u0  = blockIdx.x * 4;
    unsigned* bar = g_bar;

    // ---- prologue: split 3 W matrices; hi-frags resident, lo tiles in smem ---
    frag_b whi[3][4];
    const float* Wsrcs[3] = {Whh0, Wih1, Whh1};
#pragma unroll
    for (int m = 0; m < 3; ++m) {
        const float* Wsrc = Wsrcs[m];
        __nv_bfloat16* loT = WloS + m * 16 * PWE;
#pragma unroll 4
        for (int i = 0; i < 32; ++i) {
            int idx = tid + i * 256;               // 16 rows x 512 k
            int r = idx >> 9, k = idx & 511;
            float v = Wsrc[(size_t)((r >> 2) * Hx + u0 + (r & 3)) * Hx + k];
            __nv_bfloat16 hi = __float2bfloat16(v);
            AsmHi[r * PWE + k] = hi;
            loT[r * PWE + k] = __float2bfloat16(v - __bfloat162float(hi));
        }
        __syncthreads();
#pragma unroll
        for (int j = 0; j < 4; ++j)
            wmma::load_matrix_sync(whi[m][j], AsmHi + kb + j * 16, PWE);
        __syncthreads();
    }
    if (tid < 32) {
        int g = (tid >> 2) & 3, u = tid & 3;
        bsm[tid] = (tid < 16)
            ? (bih0[g * Hx + u0 + u] + bhh0[g * Hx + u0 + u])
            : (bih1[g * Hx + u0 + u] + bhh1[g * Hx + u0 + u]);
    }
    if (tid < 128) {
#pragma unroll
        for (int u = 0; u < 4; ++u) csm[tid * 4 + u] = 0.f;  // [2][64][4] flat
    }
    __syncthreads();

    // ---- main pipeline loop: 513 ticks ---------------------------------------
    for (int t = 0; t <= Sx; ++t) {
        const bool l0   = (t < Sx);
        const bool hasA = (t >= 1);
        const bool hasB = (t >= 2);

        // prefetch xg for L0 gate threads
        float4 xf0, xf1, xf2, xf3;
        if (l0 && tid < 64) {
            const float* xp = xg + ((size_t)(t * Bx + tid)) * Gx + u0;
            xf0 = __ldcg((const float4*)(xp));
            xf1 = __ldcg((const float4*)(xp + Hx));
            xf2 = __ldcg((const float4*)(xp + 2 * Hx));
            xf3 = __ldcg((const float4*)(xp + 3 * Hx));
        }

        frag_c aL0[4], aL1[4];
#pragma unroll
        for (int mt = 0; mt < 4; ++mt) {
            wmma::fill_fragment(aL0[mt], 0.f);
            wmma::fill_fragment(aL1[mt], 0.f);
        }

        if (hasA) {
            // issue h1[t-1] hi+lo
            stage_issue(sHi, g_h1Hi[(t - 1) & 1], tid);    // g1
            stage_issue(sLo, g_h1Lo[(t - 1) & 1], tid);    // g2
            CP_WAIT1(); __syncthreads();                   // hi(A) ready

            // ---- HI-A passes: ah x {whi0, wlo0, whi1, wlo1} -------------------
#pragma unroll
            for (int j = 0; j < 4; ++j) {
                frag_a ah[4];
#pragma unroll
                for (int mt = 0; mt < 4; ++mt)
                    wmma::load_matrix_sync(ah[mt], AsmHi + mt * 16 * PWE + kb + j * 16, PWE);
                if (l0) {
#pragma unroll
                    for (int mt = 0; mt < 4; ++mt)
                        wmma::mma_sync(aL0[mt], ah[mt], whi[0][j], aL0[mt]);
                    frag_b wl0;
                    wmma::load_matrix_sync(wl0, WloS + 0 * 16 * PWE + kb + j * 16, PWE);
#pragma unroll
                    for (int mt = 0; mt < 4; ++mt)
                        wmma::mma_sync(aL0[mt], ah[mt], wl0, aL0[mt]);
                }
#pragma unroll
                for (int mt = 0; mt < 4; ++mt)
                    wmma::mma_sync(aL1[mt], ah[mt], whi[1][j], aL1[mt]);
                frag_b wl1;
                wmma::load_matrix_sync(wl1, WloS + 1 * 16 * PWE + kb + j * 16, PWE);
#pragma unroll
                for (int mt = 0; mt < 4; ++mt)
                    wmma::mma_sync(aL1[mt], ah[mt], wl1, aL1[mt]);
            }
            __syncthreads();                               // done reading AHi

            // overlap: bring h2hi[t-2] into the freed hi buffer
            if (hasB) { stage_issue(sHi, g_h2Hi[t & 1], tid); CP_WAIT1(); }
            else      { CP_WAIT0(); }
            __syncthreads();                               // lo(A) ready

            // ---- LO-A pass: al x {whi0, whi1} --------------------------------
#pragma unroll
            for (int j = 0; j < 4; ++j) {
                frag_a al[4];
#pragma unroll
                for (int mt = 0; mt < 4; ++mt)
                    wmma::load_matrix_sync(al[mt], AsmLo + mt * 16 * PWE + kb + j * 16, PWE);
                if (l0) {
#pragma unroll
                    for (int mt = 0; mt < 4; ++mt)
                        wmma::mma_sync(aL0[mt], al[mt], whi[0][j], aL0[mt]);
                }
#pragma unroll
                for (int mt = 0; mt < 4; ++mt)
                    wmma::mma_sync(aL1[mt], al[mt], whi[1][j], aL1[mt]);
            }
            __syncthreads();                               // done reading ALo

            if (hasB) {
                stage_issue(sLo, g_h2Lo[t & 1], tid);      // lo(B) into freed lo buffer
                CP_WAIT1(); __syncthreads();               // hi(B) ready

                // ---- HI-B passes: ah x {whi2, wlo2} ---------------------------
#pragma unroll
                for (int j = 0; j < 4; ++j) {
                    frag_a ah[4];
#pragma unroll
                    for (int mt = 0; mt < 4; ++mt)
                        wmma::load_matrix_sync(ah[mt], AsmHi + mt * 16 * PWE + kb + j * 16, PWE);
#pragma unroll
                    for (int mt = 0; mt < 4; ++mt)
                        wmma::mma_sync(aL1[mt], ah[mt], whi[2][j], aL1[mt]);
                    frag_b wl2;
                    wmma::load_matrix_sync(wl2, WloS + 2 * 16 * PWE + kb + j * 16, PWE);
#pragma unroll
                    for (int mt = 0; mt < 4; ++mt)
                        wmma::mma_sync(aL1[mt], ah[mt], wl2, aL1[mt]);
                }
                CP_WAIT0(); __syncthreads();               // lo(B) ready (+ done AHi)

                // ---- LO-B pass: al x whi2 -------------------------------------
#pragma unroll
                for (int j = 0; j < 4; ++j) {
                    frag_a al[4];
#pragma unroll
                    for (int mt = 0; mt < 4; ++mt)
                        wmma::load_matrix_sync(al[mt], AsmLo + mt * 16 * PWE + kb + j * 16, PWE);
#pragma unroll
                    for (int mt = 0; mt < 4; ++mt)
                        wmma::mma_sync(aL1[mt], al[mt], whi[2][j], aL1[mt]);
                }
                __syncthreads();                           // done reading ALo
            }

            // ---- partial store + 8-way reduce --------------------------------
#pragma unroll
            for (int mt = 0; mt < 4; ++mt) {
                wmma::store_matrix_sync(P + wid * 2304 + mt * 16 * 36, aL0[mt],
                                        36, wmma::mem_row_major);
                wmma::store_matrix_sync(P + wid * 2304 + mt * 16 * 36 + 16, aL1[mt],
                                        36, wmma::mem_row_major);
            }
            __syncthreads();
#pragma unroll
            for (int i = 0; i < 8; ++i) {
                int cell = tid + i * 256;
                int b = cell >> 5, r = cell & 31;
                float v = 0.f;
#pragma unroll
                for (int w = 0; w < 8; ++w) v += P[w * 2304 + b * 36 + r];
                gsm[r * 65 + b] = v;
            }
            __syncthreads();
        }

        // ---- gates: tid<64 -> L0 batch b, 64..127 -> L1 batch b-64 ----------
        if (tid < 64 && l0) {
            const int b = tid;
            float pre[4][4];
#pragma unroll
            for (int u = 0; u < 4; ++u) {
                pre[0][u] = (hasA ? gsm[(0  + u) * 65 + b] : 0.f) + bsm[0  + u];
                pre[1][u] = (hasA ? gsm[(4  + u) * 65 + b] : 0.f) + bsm[4  + u];
                pre[2][u] = (hasA ? gsm[(8  + u) * 65 + b] : 0.f) + bsm[8  + u];
                pre[3][u] = (hasA ? gsm[(12 + u) * 65 + b] : 0.f) + bsm[12 + u];
            }
            pre[0][0] += xf0.x; pre[0][1] += xf0.y; pre[0][2] += xf0.z; pre[0][3] += xf0.w;
            pre[1][0] += xf1.x; pre[1][1] += xf1.y; pre[1][2] += xf1.z; pre[1][3] += xf1.w;
            pre[2][0] += xf2.x; pre[2][1] += xf2.y; pre[2][2] += xf2.z; pre[2][3] += xf2.w;
            pre[3][0] += xf3.x; pre[3][1] += xf3.y; pre[3][2] += xf3.z; pre[3][3] += xf3.w;
            __nv_bfloat16 hp[4], lp[4];
#pragma unroll
            for (int u = 0; u < 4; ++u) {
                float ig = sigf(pre[0][u]);
                float fg = sigf(pre[1][u]);
                float gg = tanhap(pre[2][u]);
                float og = sigf(pre[3][u]);
                float c  = csm[b * 4 + u];
                c = fg * c + ig * gg;
                csm[b * 4 + u] = c;
                float h = og * tanhap(c);
                hp[u] = __float2bfloat16(h);
                lp[u] = __float2bfloat16(h - __bfloat162float(hp[u]));
            }
            *(uint2*)(g_h1Hi[t & 1] + b * Hx + u0) = *(uint2*)hp;
            *(uint2*)(g_h1Lo[t & 1] + b * Hx + u0) = *(uint2*)lp;
        } else if (tid >= 64 && tid < 128 && hasA) {
            const int b = tid - 64;
            float hv[4];
            __nv_bfloat16 hp[4], lp[4];
#pragma unroll
            for (int u = 0; u < 4; ++u) {
                float ig = sigf(gsm[(16 + u) * 65 + b] + bsm[16 + u]);
                float fg = sigf(gsm[(20 + u) * 65 + b] + bsm[20 + u]);
                float gg = tanhap(gsm[(24 + u) * 65 + b] + bsm[24 + u]);
                float og = sigf(gsm[(28 + u) * 65 + b] + bsm[28 + u]);
                float c  = csm[256 + b * 4 + u];
                c = fg * c + ig * gg;
                csm[256 + b * 4 + u] = c;
                hv[u] = og * tanhap(c);
                hp[u] = __float2bfloat16(hv[u]);
                lp[u] = __float2bfloat16(hv[u] - __bfloat162float(hp[u]));
            }
            *(uint2*)(g_h2Hi[(t - 1) & 1] + b * Hx + u0) = *(uint2*)hp;
            *(uint2*)(g_h2Lo[(t - 1) & 1] + b * Hx + u0) = *(uint2*)lp;
            if (t == Sx)   // fp32 h2 needed only for the final FC
                *(float4*)(g_h2C + b * Hx + u0) = make_float4(hv[0], hv[1], hv[2], hv[3]);
        }

        // ---- grid barrier ----------------------------------------------------
        __syncthreads();
        if (tid == 0) {
            __threadfence();
            atomicAdd(bar, 1u);
            unsigned target = 128u * (unsigned)(t + 1);
            while (*((volatile unsigned*)bar) < target) {}
            __threadfence();
        }
        __syncthreads();
    }
}

// ---------------- final FC ---------------------------------------------------
__global__ void fc_kernel(const float* __restrict__ hC, const float* __restrict__ fw,
                          const float* __restrict__ fb, float* __restrict__ out)
{
    __shared__ float hb[Hx];
    int b = blockIdx.x;
    int o = threadIdx.x;
    for (int j = threadIdx.x; j < Hx; j += OUTx) hb[j] = hC[(size_t)b * Hx + j];
    __syncthreads();
    float acc = fb[o];
    const float* wr = fw + (size_t)o * Hx;
#pragma unroll 4
    for (int j = 0; j < Hx; j += 4) {
        float4 w = *(const float4*)(wr + j);
        float4 h = *(const float4*)(hb + j);
        acc += w.x * h.x + w.y * h.y + w.z * h.z + w.w * h.w;
    }
    out[b * OUTx + o] = acc;
}

// ---------------- launch ------------------------------------------------------
extern "C" void kernel_launch(void* const* d_in, const int* in_sizes, int n_in,
                              void* d_out, int out_size)
{
    const float* x    = (const float*)d_in[0];
    const float* Wih0 = (const float*)d_in[1];
    const float* Whh0 = (const float*)d_in[2];
    const float* bih0 = (const float*)d_in[3];
    const float* bhh0 = (const float*)d_in[4];
    const float* Wih1 = (const float*)d_in[5];
    const float* Whh1 = (const float*)d_in[6];
    const float* bih1 = (const float*)d_in[7];
    const float* bhh1 = (const float*)d_in[8];
    const float* fcw  = (const float*)d_in[9];
    const float* fcb  = (const float*)d_in[10];
    float* out = (float*)d_out;

    cudaFuncSetAttribute((const void*)fused_scan,
                         cudaFuncAttributeMaxDynamicSharedMemorySize, FUSED_SMEM);

    void *xg_p, *a2_p, *w2_p, *h2c_p;
    cudaGetSymbolAddress(&xg_p, g_xg);
    cudaGetSymbolAddress(&a2_p, g_A2);
    cudaGetSymbolAddress(&w2_p, g_W2);
    cudaGetSymbolAddress(&h2c_p, g_h2C);

    init_kernel<<<1, 32>>>();

    // layer-0 input projection on tensor cores (split-bf16, 3-pass)
    conv_w_kernel<<<Gx, 128>>>(Wih0, (__nv_bfloat16*)w2_p, Dx);
    conv_a_kernel<<<Sx * Bx, 128>>>(x, (__nv_bfloat16*)a2_p, Dx);
    dim3 mgrid(Gx / 128, (Sx * Bx) / 128);   // (16, 256)
    wmma_gemm_kernel<<<mgrid, 256>>>(
        (const __nv_bfloat16*)a2_p, (const __nv_bfloat16*)w2_p,
        (float*)xg_p, 3 * Dx);

    // balanced fused 2-layer pipelined scan (513 ticks, 128 persistent CTAs)
    fused_scan<<<128, 256, FUSED_SMEM>>>(
        (const float*)xg_p, Whh0, Wih1, Whh1, bih0, bhh0, bih1, bhh1);

    fc_kernel<<<Bx, OUTx>>>((const float*)h2c_p, fcw, fcb, out);
}

// round 16
// speedup vs baseline: 1.3356x; 1.0014x over previous
#include <cuda_runtime.h>
#include <cuda_bf16.h>
#include <mma.h>
#include <cstdint>
#include <cstddef>

using namespace nvcuda;

#define Bx   64
#define Sx   512
#define Dx   256
#define Hx   512
#define Gx   2048   // 4*H
#define OUTx 128
#define HB   (Bx * Hx)   // 32768

// ---------------- scratch (static device allocations are the allowed path) ---
__device__ float g_xg[(size_t)Sx * Bx * Gx];                 // layer-0 gate preacts (no bias)
__device__ __align__(16) __nv_bfloat16 g_h1Hi[2][HB];        // h1 double-buffered hi/lo
__device__ __align__(16) __nv_bfloat16 g_h1Lo[2][HB];
__device__ __align__(16) __nv_bfloat16 g_h2Hi[2][HB];        // h2 double-buffered hi/lo
__device__ __align__(16) __nv_bfloat16 g_h2Lo[2][HB];
__device__ float g_h2C[HB];                                  // h2 fp32 [b][j] for FC
__device__ unsigned g_bar[1];
__device__ __nv_bfloat16 g_A2[(size_t)Sx * Bx * 3 * Dx];     // split-A for gemm0
__device__ __nv_bfloat16 g_W2[(size_t)Gx * 3 * Dx];          // split-W for gemm0

__global__ void init_kernel() { if (threadIdx.x == 0) g_bar[0] = 0u; }

// ---------------- cp.async helpers -------------------------------------------
#define CP16(dst, src) \
    asm volatile("cp.async.cg.shared.global [%0], [%1], 16;" :: "r"(dst), "l"(src))
#define CP_COMMIT() asm volatile("cp.async.commit_group;" ::: "memory")
#define CP_WAIT0()  asm volatile("cp.async.wait_group 0;" ::: "memory")
#define CP_WAIT1()  asm volatile("cp.async.wait_group 1;" ::: "memory")

// ---------------- fp32 -> (hi,lo) bf16 split conversions ---------------------
__global__ void conv_w_kernel(const float* __restrict__ W, __nv_bfloat16* __restrict__ W2, int K)
{
    int n = blockIdx.x;
    const float* src = W + (size_t)n * K;
    __nv_bfloat16* dst = W2 + (size_t)n * 3 * K;
    for (int k = threadIdx.x; k < K; k += blockDim.x) {
        float v = src[k];
        __nv_bfloat16 hi = __float2bfloat16(v);
        __nv_bfloat16 lo = __float2bfloat16(v - __bfloat162float(hi));
        dst[k] = hi; dst[K + k] = lo; dst[2 * K + k] = hi;
    }
}

__global__ void conv_a_kernel(const float* __restrict__ A, __nv_bfloat16* __restrict__ A2, int K)
{
    int m = blockIdx.x;   // m = s*64 + b ; A is x[b][s][k]
    const float* src = A + (size_t)(m & 63) * (Sx * Dx) + (size_t)(m >> 6) * Dx;
    __nv_bfloat16* dst = A2 + (size_t)m * 3 * K;
    for (int k = threadIdx.x; k < K; k += blockDim.x) {
        float v = src[k];
        __nv_bfloat16 hi = __float2bfloat16(v);
        __nv_bfloat16 lo = __float2bfloat16(v - __bfloat162float(hi));
        dst[k] = hi; dst[K + k] = hi; dst[2 * K + k] = lo;
    }
}

// ---------------- HMMA (wmma) GEMM for layer-0 input projection ---------------
// cp.async double-buffered; <=128 regs so 2 CTAs/SM.
#define LDP 40

__global__ void __launch_bounds__(256, 2) wmma_gemm_kernel(
    const __nv_bfloat16* __restrict__ A2, const __nv_bfloat16* __restrict__ W2,
    float* __restrict__ C, int Ktot)
{
    __shared__ __align__(16) __nv_bfloat16 As[2][128 * LDP];
    __shared__ __align__(16) __nv_bfloat16 Bs[2][128 * LDP];

    const int tid = threadIdx.x;
    const int wid = tid >> 5;
    const int m0 = blockIdx.y * 128;
    const int n0 = blockIdx.x * 128;
    const int wm = (wid >> 2) * 64;
    const int wn = (wid & 3) * 32;

    wmma::fragment<wmma::accumulator, 16, 16, 16, float> acc[4][2];
#pragma unroll
    for (int i = 0; i < 4; ++i)
#pragma unroll
        for (int j = 0; j < 2; ++j) wmma::fill_fragment(acc[i][j], 0.f);

    const int ca = tid, cb = tid + 256;
    const int ra = ca >> 2, qa = ca & 3;
    const int rb = cb >> 2, qb = cb & 3;
    const char* Ag = (const char*)A2;
    const char* Bg = (const char*)W2;
    const size_t aoff0 = ((size_t)(m0 + ra) * Ktot + qa * 8) * 2;
    const size_t aoff1 = ((size_t)(m0 + rb) * Ktot + qb * 8) * 2;
    const size_t boff0 = ((size_t)(n0 + ra) * Ktot + qa * 8) * 2;
    const size_t boff1 = ((size_t)(n0 + rb) * Ktot + qb * 8) * 2;
    const int s0 = ra * (LDP * 2) + qa * 16;
    const int s1 = rb * (LDP * 2) + qb * 16;

    uint32_t sA[2], sB[2];
    sA[0] = (uint32_t)__cvta_generic_to_shared(As[0]);
    sA[1] = (uint32_t)__cvta_generic_to_shared(As[1]);
    sB[0] = (uint32_t)__cvta_generic_to_shared(Bs[0]);
    sB[1] = (uint32_t)__cvta_generic_to_shared(Bs[1]);

    const int T = Ktot >> 5;
    {
        CP16(sA[0] + s0, Ag + aoff0);
        CP16(sA[0] + s1, Ag + aoff1);
        CP16(sB[0] + s0, Bg + boff0);
        CP16(sB[0] + s1, Bg + boff1);
        CP_COMMIT();
    }

    for (int t = 0; t < T; ++t) {
        const int buf = t & 1;
        const bool more = (t + 1 < T);
        if (more) {
            size_t ko = (size_t)(t + 1) * 64;
            const int nb = buf ^ 1;
            CP16(sA[nb] + s0, Ag + aoff0 + ko);
            CP16(sA[nb] + s1, Ag + aoff1 + ko);
            CP16(sB[nb] + s0, Bg + boff0 + ko);
            CP16(sB[nb] + s1, Bg + boff1 + ko);
            CP_COMMIT();
            CP_WAIT1();
        } else {
            CP_WAIT0();
        }
        __syncthreads();
#pragma unroll
        for (int ks = 0; ks < 2; ++ks) {
            wmma::fragment<wmma::matrix_a, 16, 16, 16, __nv_bfloat16, wmma::row_major> af[4];
            wmma::fragment<wmma::matrix_b, 16, 16, 16, __nv_bfloat16, wmma::col_major> bf[2];
#pragma unroll
            for (int i = 0; i < 4; ++i)
                wmma::load_matrix_sync(af[i], &As[buf][(wm + i * 16) * LDP + ks * 16], LDP);
#pragma unroll
            for (int j = 0; j < 2; ++j)
                wmma::load_matrix_sync(bf[j], &Bs[buf][(wn + j * 16) * LDP + ks * 16], LDP);
#pragma unroll
            for (int i = 0; i < 4; ++i)
#pragma unroll
                for (int j = 0; j < 2; ++j)
                    wmma::mma_sync(acc[i][j], af[i], bf[j], acc[i][j]);
        }
        __syncthreads();
    }

#pragma unroll
    for (int i = 0; i < 4; ++i)
#pragma unroll
        for (int j = 0; j < 2; ++j)
            wmma::store_matrix_sync(
                C + (size_t)(m0 + wm + i * 16) * Gx + n0 + wn + j * 16,
                acc[i][j], Gx, wmma::mem_row_major);
}

// ---------------- balanced fused 2-layer pipelined LSTM scan (R13) ------------
// 128 identical CTAs; each owns 4 hidden units of BOTH layers. Tick t: L0 step t,
// L1 step t-1. cp.async 4-phase pipeline overlaps tile staging with mma.
#define PWE    520
#define SM_AHI 0
#define SM_ALO 66560
#define SM_WLO 133120                  // [3][16][520] bf16 W-lo tiles (resident)
#define SM_GSM 183040                  // [32][65] floats
#define SM_CSM 191360                  // [2][64][4] floats
#define SM_BSM 193408                  // [32] floats
#define FUSED_SMEM 193664

typedef wmma::fragment<wmma::matrix_a, 16, 16, 16, __nv_bfloat16, wmma::row_major> frag_a;
typedef wmma::fragment<wmma::matrix_b, 16, 16, 16, __nv_bfloat16, wmma::col_major> frag_b;
typedef wmma::fragment<wmma::accumulator, 16, 16, 16, float> frag_c;

__device__ __forceinline__ float tanhap(float x) {
    float y; asm("tanh.approx.f32 %0, %1;" : "=f"(y) : "f"(x)); return y;
}
__device__ __forceinline__ float sigf(float x) {
    return fmaf(tanhap(x * 0.5f), 0.5f, 0.5f);
}

// issue async stage of 64x512 bf16 [b][j] tile into padded smem (1040B rows)
__device__ __forceinline__ void stage_issue(uint32_t dstb, const __nv_bfloat16* src, int tid) {
#pragma unroll
    for (int i = 0; i < 16; ++i) {
        int c = tid + i * 256;
        int row = c >> 6, col = c & 63;
        CP16(dstb + row * 1040 + col * 16, src + row * Hx + col * 8);
    }
    CP_COMMIT();
}

__global__ void __launch_bounds__(256, 1) fused_scan(
    const float* __restrict__ xg,
    const float* __restrict__ Whh0, const float* __restrict__ Wih1,
    const float* __restrict__ Whh1,
    const float* __restrict__ bih0, const float* __restrict__ bhh0,
    const float* __restrict__ bih1, const float* __restrict__ bhh1)
{
    extern __shared__ char sm[];
    __nv_bfloat16* AsmHi = (__nv_bfloat16*)(sm + SM_AHI);
    __nv_bfloat16* AsmLo = (__nv_bfloat16*)(sm + SM_ALO);
    __nv_bfloat16* WloS  = (__nv_bfloat16*)(sm + SM_WLO);
    float* gsm = (float*)(sm + SM_GSM);
    float* csm = (float*)(sm + SM_CSM);
    float* bsm = (float*)(sm + SM_BSM);
    float* P   = (float*)(sm + SM_AHI);            // partials alias A region
    const uint32_t sHi = (uint32_t)__cvta_generic_to_shared(AsmHi);
    const uint32_t sLo = (uint32_t)__cvta_generic_to_shared(AsmLo);

    const int tid = threadIdx.x;
    const int wid = tid >> 5;
    const int kb  = wid * 64;
    const int u0  = blockIdx.x * 4;
    unsigned* bar = g_bar;

    // ---- prologue: split 3 W matrices; hi-frags resident, lo tiles in smem ---
    frag_b whi[3][4];
    const float* Wsrcs[3] = {Whh0, Wih1, Whh1};
#pragma unroll
    for (int m = 0; m < 3; ++m) {
        const float* Wsrc = Wsrcs[m];
        __nv_bfloat16* loT = WloS + m * 16 * PWE;
#pragma unroll 4
        for (int i = 0; i < 32; ++i) {
            int idx = tid + i * 256;               // 16 rows x 512 k
            int r = idx >> 9, k = idx & 511;
            float v = Wsrc[(size_t)((r >> 2) * Hx + u0 + (r & 3)) * Hx + k];
            __nv_bfloat16 hi = __float2bfloat16(v);
            AsmHi[r * PWE + k] = hi;
            loT[r * PWE + k] = __float2bfloat16(v - __bfloat162float(hi));
        }
        __syncthreads();
#pragma unroll
        for (int j = 0; j < 4; ++j)
            wmma::load_matrix_sync(whi[m][j], AsmHi + kb + j * 16, PWE);
        __syncthreads();
    }
    if (tid < 32) {
        int g = (tid >> 2) & 3, u = tid & 3;
        bsm[tid] = (tid < 16)
            ? (bih0[g * Hx + u0 + u] + bhh0[g * Hx + u0 + u])
            : (bih1[g * Hx + u0 + u] + bhh1[g * Hx + u0 + u]);
    }
    if (tid < 128) {
#pragma unroll
        for (int u = 0; u < 4; ++u) csm[tid * 4 + u] = 0.f;  // [2][64][4] flat
    }
    __syncthreads();

    // ---- main pipeline loop: 513 ticks ---------------------------------------
    for (int t = 0; t <= Sx; ++t) {
        const bool l0   = (t < Sx);
        const bool hasA = (t >= 1);
        const bool hasB = (t >= 2);

        // prefetch xg for L0 gate threads
        float4 xf0, xf1, xf2, xf3;
        if (l0 && tid < 64) {
            const float* xp = xg + ((size_t)(t * Bx + tid)) * Gx + u0;
            xf0 = __ldcg((const float4*)(xp));
            xf1 = __ldcg((const float4*)(xp + Hx));
            xf2 = __ldcg((const float4*)(xp + 2 * Hx));
            xf3 = __ldcg((const float4*)(xp + 3 * Hx));
        }

        frag_c aL0[4], aL1[4];
#pragma unroll
        for (int mt = 0; mt < 4; ++mt) {
            wmma::fill_fragment(aL0[mt], 0.f);
            wmma::fill_fragment(aL1[mt], 0.f);
        }

        if (hasA) {
            // issue h1[t-1] hi+lo
            stage_issue(sHi, g_h1Hi[(t - 1) & 1], tid);    // g1
            stage_issue(sLo, g_h1Lo[(t - 1) & 1], tid);    // g2
            CP_WAIT1(); __syncthreads();                   // hi(A) ready

            // ---- HI-A passes: ah x {whi0, wlo0, whi1, wlo1} -------------------
#pragma unroll
            for (int j = 0; j < 4; ++j) {
                frag_a ah[4];
#pragma unroll
                for (int mt = 0; mt < 4; ++mt)
                    wmma::load_matrix_sync(ah[mt], AsmHi + mt * 16 * PWE + kb + j * 16, PWE);
                if (l0) {
#pragma unroll
                    for (int mt = 0; mt < 4; ++mt)
                        wmma::mma_sync(aL0[mt], ah[mt], whi[0][j], aL0[mt]);
                    frag_b wl0;
                    wmma::load_matrix_sync(wl0, WloS + 0 * 16 * PWE + kb + j * 16, PWE);
#pragma unroll
                    for (int mt = 0; mt < 4; ++mt)
                        wmma::mma_sync(aL0[mt], ah[mt], wl0, aL0[mt]);
                }
#pragma unroll
                for (int mt = 0; mt < 4; ++mt)
                    wmma::mma_sync(aL1[mt], ah[mt], whi[1][j], aL1[mt]);
                frag_b wl1;
                wmma::load_matrix_sync(wl1, WloS + 1 * 16 * PWE + kb + j * 16, PWE);
#pragma unroll
                for (int mt = 0; mt < 4; ++mt)
                    wmma::mma_sync(aL1[mt], ah[mt], wl1, aL1[mt]);
            }
            __syncthreads();                               // done reading AHi

            // overlap: bring h2hi[t-2] into the freed hi buffer
            if (hasB) { stage_issue(sHi, g_h2Hi[t & 1], tid); CP_WAIT1(); }
            else      { CP_WAIT0(); }
            __syncthreads();                               // lo(A) ready

            // ---- LO-A pass: al x {whi0, whi1} --------------------------------
#pragma unroll
            for (int j = 0; j < 4; ++j) {
                frag_a al[4];
#pragma unroll
                for (int mt = 0; mt < 4; ++mt)
                    wmma::load_matrix_sync(al[mt], AsmLo + mt * 16 * PWE + kb + j * 16, PWE);
                if (l0) {
#pragma unroll
                    for (int mt = 0; mt < 4; ++mt)
                        wmma::mma_sync(aL0[mt], al[mt], whi[0][j], aL0[mt]);
                }
#pragma unroll
                for (int mt = 0; mt < 4; ++mt)
                    wmma::mma_sync(aL1[mt], al[mt], whi[1][j], aL1[mt]);
            }
            __syncthreads();                               // done reading ALo

            if (hasB) {
                stage_issue(sLo, g_h2Lo[t & 1], tid);      // lo(B) into freed lo buffer
                CP_WAIT1(); __syncthreads();               // hi(B) ready

                // ---- HI-B passes: ah x {whi2, wlo2} ---------------------------
#pragma unroll
                for (int j = 0; j < 4; ++j) {
                    frag_a ah[4];
#pragma unroll
                    for (int mt = 0; mt < 4; ++mt)
                        wmma::load_matrix_sync(ah[mt], AsmHi + mt * 16 * PWE + kb + j * 16, PWE);
#pragma unroll
                    for (int mt = 0; mt < 4; ++mt)
                        wmma::mma_sync(aL1[mt], ah[mt], whi[2][j], aL1[mt]);
                    frag_b wl2;
                    wmma::load_matrix_sync(wl2, WloS + 2 * 16 * PWE + kb + j * 16, PWE);
#pragma unroll
                    for (int mt = 0; mt < 4; ++mt)
                        wmma::mma_sync(aL1[mt], ah[mt], wl2, aL1[mt]);
                }
                CP_WAIT0(); __syncthreads();               // lo(B) ready (+ done AHi)

                // ---- LO-B pass: al x whi2 -------------------------------------
#pragma unroll
                for (int j = 0; j < 4; ++j) {
                    frag_a al[4];
#pragma unroll
                    for (int mt = 0; mt < 4; ++mt)
                        wmma::load_matrix_sync(al[mt], AsmLo + mt * 16 * PWE + kb + j * 16, PWE);
#pragma unroll
                    for (int mt = 0; mt < 4; ++mt)
                        wmma::mma_sync(aL1[mt], al[mt], whi[2][j], aL1[mt]);
                }
                __syncthreads();                           // done reading ALo
            }

            // ---- partial store + 8-way reduce --------------------------------
#pragma unroll
            for (int mt = 0; mt < 4; ++mt) {
                wmma::store_matrix_sync(P + wid * 2304 + mt * 16 * 36, aL0[mt],
                                        36, wmma::mem_row_major);
                wmma::store_matrix_sync(P + wid * 2304 + mt * 16 * 36 + 16, aL1[mt],
                                        36, wmma::mem_row_major);
            }
            __syncthreads();
#pragma unroll
            for (int i = 0; i < 8; ++i) {
                int cell = tid + i * 256;
                int b = cell >> 5, r = cell & 31;
                float v = 0.f;
#pragma unroll
                for (int w = 0; w < 8; ++w) v += P[w * 2304 + b * 36 + r];
                gsm[r * 65 + b] = v;
            }
            __syncthreads();
        }

        // ---- gates: tid<64 -> L0 batch b, 64..127 -> L1 batch b-64 ----------
        if (tid < 64 && l0) {
            const int b = tid;
            float pre[4][4];
#pragma unroll
            for (int u = 0; u < 4; ++u) {
                pre[0][u] = (hasA ? gsm[(0  + u) * 65 + b] : 0.f) + bsm[0  + u];
                pre[1][u] = (hasA ? gsm[(4  + u) * 65 + b] : 0.f) + bsm[4  + u];
                pre[2][u] = (hasA ? gsm[(8  + u) * 65 + b] : 0.f) + bsm[8  + u];
                pre[3][u] = (hasA ? gsm[(12 + u) * 65 + b] : 0.f) + bsm[12 + u];
            }
            pre[0][0] += xf0.x; pre[0][1] += xf0.y; pre[0][2] += xf0.z; pre[0][3] += xf0.w;
            pre[1][0] += xf1.x; pre[1][1] += xf1.y; pre[1][2] += xf1.z; pre[1][3] += xf1.w;
            pre[2][0] += xf2.x; pre[2][1] += xf2.y; pre[2][2] += xf2.z; pre[2][3] += xf2.w;
            pre[3][0] += xf3.x; pre[3][1] += xf3.y; pre[3][2] += xf3.z; pre[3][3] += xf3.w;
            __nv_bfloat16 hp[4], lp[4];
#pragma unroll
            for (int u = 0; u < 4; ++u) {
                float ig = sigf(pre[0][u]);
                float fg = sigf(pre[1][u]);
                float gg = tanhap(pre[2][u]);
                float og = sigf(pre[3][u]);
                float c  = csm[b * 4 + u];
                c = fg * c + ig * gg;
                csm[b * 4 + u] = c;
                float h = og * tanhap(c);
                hp[u] = __float2bfloat16(h);
                lp[u] = __float2bfloat16(h - __bfloat162float(hp[u]));
            }
            *(uint2*)(g_h1Hi[t & 1] + b * Hx + u0) = *(uint2*)hp;
            *(uint2*)(g_h1Lo[t & 1] + b * Hx + u0) = *(uint2*)lp;
        } else if (tid >= 64 && tid < 128 && hasA) {
            const int b = tid - 64;
            float hv[4];
            __nv_bfloat16 hp[4], lp[4];
#pragma unroll
            for (int u = 0; u < 4; ++u) {
                float ig = sigf(gsm[(16 + u) * 65 + b] + bsm[16 + u]);
                float fg = sigf(gsm[(20 + u) * 65 + b] + bsm[20 + u]);
                float gg = tanhap(gsm[(24 + u) * 65 + b] + bsm[24 + u]);
                float og = sigf(gsm[(28 + u) * 65 + b] + bsm[28 + u]);
                float c  = csm[256 + b * 4 + u];
                c = fg * c + ig * gg;
                csm[256 + b * 4 + u] = c;
                hv[u] = og * tanhap(c);
                hp[u] = __float2bfloat16(hv[u]);
                lp[u] = __float2bfloat16(hv[u] - __bfloat162float(hp[u]));
            }
            *(uint2*)(g_h2Hi[(t - 1) & 1] + b * Hx + u0) = *(uint2*)hp;
            *(uint2*)(g_h2Lo[(t - 1) & 1] + b * Hx + u0) = *(uint2*)lp;
            if (t == Sx)   // fp32 h2 needed only for the final FC
                *(float4*)(g_h2C + b * Hx + u0) = make_float4(hv[0], hv[1], hv[2], hv[3]);
        }

        // ---- grid barrier ----------------------------------------------------
        __syncthreads();
        if (tid == 0) {
            __threadfence();
            atomicAdd(bar, 1u);
            unsigned target = 128u * (unsigned)(t + 1);
            while (*((volatile unsigned*)bar) < target) {}
            __threadfence();
        }
        __syncthreads();
    }
}

// ---------------- final FC ---------------------------------------------------
__global__ void fc_kernel(const float* __restrict__ hC, const float* __restrict__ fw,
                          const float* __restrict__ fb, float* __restrict__ out)
{
    __shared__ float hb[Hx];
    int b = blockIdx.x;
    int o = threadIdx.x;
    for (int j = threadIdx.x; j < Hx; j += OUTx) hb[j] = hC[(size_t)b * Hx + j];
    __syncthreads();
    float acc = fb[o];
    const float* wr = fw + (size_t)o * Hx;
#pragma unroll 4
    for (int j = 0; j < Hx; j += 4) {
        float4 w = *(const float4*)(wr + j);
        float4 h = *(const float4*)(hb + j);
        acc += w.x * h.x + w.y * h.y + w.z * h.z + w.w * h.w;
    }
    out[b * OUTx + o] = acc;
}

// ---------------- launch ------------------------------------------------------
extern "C" void kernel_launch(void* const* d_in, const int* in_sizes, int n_in,
                              void* d_out, int out_size)
{
    const float* x    = (const float*)d_in[0];
    const float* Wih0 = (const float*)d_in[1];
    const float* Whh0 = (const float*)d_in[2];
    const float* bih0 = (const float*)d_in[3];
    const float* bhh0 = (const float*)d_in[4];
    const float* Wih1 = (const float*)d_in[5];
    const float* Whh1 = (const float*)d_in[6];
    const float* bih1 = (const float*)d_in[7];
    const float* bhh1 = (const float*)d_in[8];
    const float* fcw  = (const float*)d_in[9];
    const float* fcb  = (const float*)d_in[10];
    float* out = (float*)d_out;

    cudaFuncSetAttribute((const void*)fused_scan,
                         cudaFuncAttributeMaxDynamicSharedMemorySize, FUSED_SMEM);

    void *xg_p, *a2_p, *w2_p, *h2c_p;
    cudaGetSymbolAddress(&xg_p, g_xg);
    cudaGetSymbolAddress(&a2_p, g_A2);
    cudaGetSymbolAddress(&w2_p, g_W2);
    cudaGetSymbolAddress(&h2c_p, g_h2C);

    init_kernel<<<1, 32>>>();

    // layer-0 input projection on tensor cores (split-bf16, 3-pass)
    conv_w_kernel<<<Gx, 128>>>(Wih0, (__nv_bfloat16*)w2_p, Dx);
    conv_a_kernel<<<Sx * Bx, 128>>>(x, (__nv_bfloat16*)a2_p, Dx);
    dim3 mgrid(Gx / 128, (Sx * Bx) / 128);   // (16, 256)
    wmma_gemm_kernel<<<mgrid, 256>>>(
        (const __nv_bfloat16*)a2_p, (const __nv_bfloat16*)w2_p,
        (float*)xg_p, 3 * Dx);

    // balanced fused 2-layer pipelined scan (513 ticks, 128 persistent CTAs)
    fused_scan<<<128, 256, FUSED_SMEM>>>(
        (const float*)xg_p, Whh0, Wih1, Whh1, bih0, bhh0, bih1, bhh1);

    fc_kernel<<<Bx, OUTx>>>((const float*)h2c_p, fcw, fcb, out);
}